// round 1
// baseline (speedup 1.0000x reference)
#include <cuda_runtime.h>
#include <cuda_bf16.h>
#include <cstdint>

// Problem constants
#define BB   2
#define SS   2048
#define EE   1024
#define HH   16
#define DD   64
#define CC   256
#define MM   (BB * SS)          // 4096 rows

// ---------------------------------------------------------------------------
// Scratch (allocation-free: __device__ globals)
// ---------------------------------------------------------------------------
__device__ float g_Q [MM * EE];
__device__ float g_K [MM * EE];
__device__ float g_V [MM * EE];
__device__ float g_AO[MM * EE];   // attention output (B,S,E)
__device__ float g_PO[MM * EE];   // attn @ Wo.T
__device__ float g_mod[BB * 2 * EE];

// ---------------------------------------------------------------------------
// SGEMM  C[M,N] = A[M,K] * B[N,K]^T   (both row-major, K contiguous: "NT")
// 128x128 block tile, BK=16, 256 threads, 8x8 register tile per thread.
// ---------------------------------------------------------------------------
__global__ __launch_bounds__(256) void sgemm_nt(const float* __restrict__ A,
                                                const float* __restrict__ B,
                                                float* __restrict__ C,
                                                int M, int N, int K)
{
    __shared__ float As[16][128];
    __shared__ float Bs[16][128];
    const int tid = threadIdx.x;
    const int tx  = tid & 15;
    const int ty  = tid >> 4;
    const int row0 = blockIdx.y * 128;
    const int col0 = blockIdx.x * 128;

    float acc[8][8];
#pragma unroll
    for (int i = 0; i < 8; i++)
#pragma unroll
        for (int j = 0; j < 8; j++) acc[i][j] = 0.f;

    for (int k0 = 0; k0 < K; k0 += 16) {
#pragma unroll
        for (int i = 0; i < 2; i++) {
            int idx = tid + i * 256;          // 0..511
            int r   = idx >> 2;               // 0..127
            int kq  = (idx & 3) * 4;          // 0,4,8,12
            float4 va = *(const float4*)(A + (size_t)(row0 + r) * K + k0 + kq);
            As[kq + 0][r] = va.x; As[kq + 1][r] = va.y;
            As[kq + 2][r] = va.z; As[kq + 3][r] = va.w;
            float4 vb = *(const float4*)(B + (size_t)(col0 + r) * K + k0 + kq);
            Bs[kq + 0][r] = vb.x; Bs[kq + 1][r] = vb.y;
            Bs[kq + 2][r] = vb.z; Bs[kq + 3][r] = vb.w;
        }
        __syncthreads();
#pragma unroll
        for (int k = 0; k < 16; k++) {
            float a[8], b[8];
            *(float4*)&a[0] = *(const float4*)&As[k][ty * 8];
            *(float4*)&a[4] = *(const float4*)&As[k][ty * 8 + 4];
            *(float4*)&b[0] = *(const float4*)&Bs[k][tx * 8];
            *(float4*)&b[4] = *(const float4*)&Bs[k][tx * 8 + 4];
#pragma unroll
            for (int i = 0; i < 8; i++)
#pragma unroll
                for (int j = 0; j < 8; j++)
                    acc[i][j] += a[i] * b[j];
        }
        __syncthreads();
    }
#pragma unroll
    for (int i = 0; i < 8; i++) {
        float* cp = C + (size_t)(row0 + ty * 8 + i) * N + col0 + tx * 8;
        *(float4*)(cp)     = make_float4(acc[i][0], acc[i][1], acc[i][2], acc[i][3]);
        *(float4*)(cp + 4) = make_float4(acc[i][4], acc[i][5], acc[i][6], acc[i][7]);
    }
}

// ---------------------------------------------------------------------------
// Flash attention, fp32, causal. One CTA = 64 query rows of one (b,h).
// 256 threads: tr = tid/16 owns rows tr*4..+3, tc = tid%16 owns cols tc*4..+3.
// Online softmax; key tiles 0..qt (causal).
// ---------------------------------------------------------------------------
#define PADR 68
#define ATTN_SMEM (4 * 64 * PADR * 4)

__global__ __launch_bounds__(256) void attn_kernel(const float* __restrict__ Q,
                                                   const float* __restrict__ Kg,
                                                   const float* __restrict__ Vg,
                                                   float* __restrict__ Og)
{
    extern __shared__ float sm[];
    float* Qk  = sm;                    // [k][row]  64 x PADR
    float* Kts = sm + 64 * PADR;        // [k][col]
    float* Vs  = sm + 2 * 64 * PADR;    // [col][d]
    float* Pt  = sm + 3 * 64 * PADR;    // [col][row]

    const int tid = threadIdx.x;
    const int tc  = tid & 15;
    const int tr  = tid >> 4;
    const int qt  = blockIdx.x;
    const int bh  = blockIdx.y;
    const int b   = bh >> 4;
    const int h   = bh & 15;
    const int q0  = qt * 64;
    const size_t base = ((size_t)b * SS) * EE + (size_t)h * DD;

    // Load Q tile transposed into Qk[k][row]
#pragma unroll
    for (int i = 0; i < 4; i++) {
        int idx = tid + i * 256;        // 0..1023
        int r   = idx >> 4;             // 0..63
        int kq  = (idx & 15) * 4;       // 0..60
        float4 v = *(const float4*)(Q + base + (size_t)(q0 + r) * EE + kq);
        Qk[(kq + 0) * PADR + r] = v.x;
        Qk[(kq + 1) * PADR + r] = v.y;
        Qk[(kq + 2) * PADR + r] = v.z;
        Qk[(kq + 3) * PADR + r] = v.w;
    }

    float m_i[4], l_i[4], o[4][4];
#pragma unroll
    for (int i = 0; i < 4; i++) {
        m_i[i] = -1e30f; l_i[i] = 0.f;
#pragma unroll
        for (int j = 0; j < 4; j++) o[i][j] = 0.f;
    }

    for (int kt = 0; kt <= qt; kt++) {
        const int k0 = kt * 64;
        __syncthreads();   // previous tile fully consumed (also covers Qk store)
#pragma unroll
        for (int i = 0; i < 4; i++) {
            int idx = tid + i * 256;
            int r   = idx >> 4;
            int kq  = (idx & 15) * 4;
            float4 vk = *(const float4*)(Kg + base + (size_t)(k0 + r) * EE + kq);
            Kts[(kq + 0) * PADR + r] = vk.x;
            Kts[(kq + 1) * PADR + r] = vk.y;
            Kts[(kq + 2) * PADR + r] = vk.z;
            Kts[(kq + 3) * PADR + r] = vk.w;
            float4 vv = *(const float4*)(Vg + base + (size_t)(k0 + r) * EE + kq);
            *(float4*)(Vs + r * PADR + kq) = vv;
        }
        __syncthreads();

        // S = Q K^T tile (64x64), 4x4 per thread
        float s[4][4];
#pragma unroll
        for (int i = 0; i < 4; i++)
#pragma unroll
            for (int j = 0; j < 4; j++) s[i][j] = 0.f;

#pragma unroll 16
        for (int k = 0; k < 64; k++) {
            float4 af = *(const float4*)(Qk  + k * PADR + tr * 4);
            float4 bf = *(const float4*)(Kts + k * PADR + tc * 4);
            float av[4] = {af.x, af.y, af.z, af.w};
            float bv[4] = {bf.x, bf.y, bf.z, bf.w};
#pragma unroll
            for (int i = 0; i < 4; i++)
#pragma unroll
                for (int j = 0; j < 4; j++)
                    s[i][j] += av[i] * bv[j];
        }

        const bool diag = (kt == qt);
#pragma unroll
        for (int i = 0; i < 4; i++) {
            int row = tr * 4 + i;
#pragma unroll
            for (int j = 0; j < 4; j++) {
                float v = s[i][j] * 0.125f;            // D^-0.5
                if (diag && (tc * 4 + j > row)) v = -1e30f;
                s[i][j] = v;
            }
        }

        // online softmax per row (16-lane groups within warp)
#pragma unroll
        for (int i = 0; i < 4; i++) {
            float mx = fmaxf(fmaxf(s[i][0], s[i][1]), fmaxf(s[i][2], s[i][3]));
#pragma unroll
            for (int off = 8; off >= 1; off >>= 1)
                mx = fmaxf(mx, __shfl_xor_sync(0xffffffffu, mx, off));
            float m_new = fmaxf(m_i[i], mx);
            float corr  = __expf(m_i[i] - m_new);
            float p0 = __expf(s[i][0] - m_new);
            float p1 = __expf(s[i][1] - m_new);
            float p2 = __expf(s[i][2] - m_new);
            float p3 = __expf(s[i][3] - m_new);
            float psum = (p0 + p1) + (p2 + p3);
#pragma unroll
            for (int off = 8; off >= 1; off >>= 1)
                psum += __shfl_xor_sync(0xffffffffu, psum, off);
            l_i[i] = l_i[i] * corr + psum;
            m_i[i] = m_new;
            o[i][0] *= corr; o[i][1] *= corr; o[i][2] *= corr; o[i][3] *= corr;
            Pt[(tc * 4 + 0) * PADR + tr * 4 + i] = p0;
            Pt[(tc * 4 + 1) * PADR + tr * 4 + i] = p1;
            Pt[(tc * 4 + 2) * PADR + tr * 4 + i] = p2;
            Pt[(tc * 4 + 3) * PADR + tr * 4 + i] = p3;
        }
        __syncthreads();

        // O += P V
#pragma unroll 16
        for (int col = 0; col < 64; col++) {
            float4 pf = *(const float4*)(Pt + col * PADR + tr * 4);
            float4 vf = *(const float4*)(Vs + col * PADR + tc * 4);
            float pv[4] = {pf.x, pf.y, pf.z, pf.w};
            float vv[4] = {vf.x, vf.y, vf.z, vf.w};
#pragma unroll
            for (int i = 0; i < 4; i++)
#pragma unroll
                for (int j = 0; j < 4; j++)
                    o[i][j] += pv[i] * vv[j];
        }
    }

#pragma unroll
    for (int i = 0; i < 4; i++) {
        float inv = 1.0f / l_i[i];
        float4 r4 = make_float4(o[i][0] * inv, o[i][1] * inv,
                                o[i][2] * inv, o[i][3] * inv);
        *(float4*)(Og + base + (size_t)(q0 + tr * 4 + i) * EE + tc * 4) = r4;
    }
}

// ---------------------------------------------------------------------------
// mod = silu(conditioning) @ Wc.T + bc      (B, 2E)
// ---------------------------------------------------------------------------
__global__ __launch_bounds__(256) void mod_kernel(const float* __restrict__ cond,
                                                  const float* __restrict__ Wc,
                                                  const float* __restrict__ bc,
                                                  float* __restrict__ mod)
{
    __shared__ float scd[CC];
    const int b = blockIdx.y;
    const int t = threadIdx.x;
    float cv = cond[b * CC + t];
    scd[t] = cv / (1.f + __expf(-cv));
    __syncthreads();
    const int j = blockIdx.x * 256 + t;        // 0..2047
    const float* w = Wc + (size_t)j * CC;
    float sum = bc[j];
#pragma unroll 8
    for (int c = 0; c < CC; c++) sum += scd[c] * w[c];
    mod[b * 2 * EE + j] = sum;
}

// ---------------------------------------------------------------------------
// AdaptiveRMSNorm + FiLM:  out = (P/rms * g) * (1+sc) + shift
// One CTA per row (4096 rows, 256 threads, 4 elems/thread).
// ---------------------------------------------------------------------------
__global__ __launch_bounds__(256) void rmsfilm_kernel(const float* __restrict__ P,
                                                      const float* __restrict__ mod,
                                                      const float* __restrict__ gscale,
                                                      float* __restrict__ out)
{
    const int m = blockIdx.x;          // 0..4095
    const int b = m >> 11;             // row / 2048
    const int t = threadIdx.x;
    const float* row = P + (size_t)m * EE;
    float4 v = *(const float4*)(row + t * 4);
    float ss = v.x * v.x + v.y * v.y + v.z * v.z + v.w * v.w;
#pragma unroll
    for (int off = 16; off >= 1; off >>= 1)
        ss += __shfl_xor_sync(0xffffffffu, ss, off);
    __shared__ float red[8];
    if ((t & 31) == 0) red[t >> 5] = ss;
    __syncthreads();
    float total = 0.f;
#pragma unroll
    for (int w = 0; w < 8; w++) total += red[w];
    float inv = rsqrtf(total * (1.0f / (float)EE) + 1e-6f);

    const int j = t * 4;
    float4 g  = *(const float4*)(gscale + j);
    float4 sh = *(const float4*)(mod + b * 2 * EE + j);
    float4 sc = *(const float4*)(mod + b * 2 * EE + EE + j);
    float4 r;
    r.x = v.x * inv * g.x * (1.f + sc.x) + sh.x;
    r.y = v.y * inv * g.y * (1.f + sc.y) + sh.y;
    r.z = v.z * inv * g.z * (1.f + sc.z) + sh.z;
    r.w = v.w * inv * g.w * (1.f + sc.w) + sh.w;
    *(float4*)(out + (size_t)m * EE + j) = r;
}

// ---------------------------------------------------------------------------
// launch
// ---------------------------------------------------------------------------
extern "C" void kernel_launch(void* const* d_in, const int* in_sizes, int n_in,
                              void* d_out, int out_size)
{
    const float* x    = (const float*)d_in[0];
    // d_in[1] = mask (bool triu k=1) — causal, reproduced analytically in-kernel
    const float* cond = (const float*)d_in[2];
    const float* Wq   = (const float*)d_in[3];
    const float* Wk   = (const float*)d_in[4];
    const float* Wv   = (const float*)d_in[5];
    const float* Wo   = (const float*)d_in[6];
    const float* rs   = (const float*)d_in[7];
    const float* Wc   = (const float*)d_in[8];
    const float* bc   = (const float*)d_in[9];
    float* out = (float*)d_out;

    float *pQ, *pK, *pV, *pAO, *pPO, *pmod;
    cudaGetSymbolAddress((void**)&pQ,   g_Q);
    cudaGetSymbolAddress((void**)&pK,   g_K);
    cudaGetSymbolAddress((void**)&pV,   g_V);
    cudaGetSymbolAddress((void**)&pAO,  g_AO);
    cudaGetSymbolAddress((void**)&pPO,  g_PO);
    cudaGetSymbolAddress((void**)&pmod, g_mod);

    cudaFuncSetAttribute(attn_kernel,
                         cudaFuncAttributeMaxDynamicSharedMemorySize, ATTN_SMEM);

    dim3 gg(EE / 128, MM / 128);   // (8, 32)
    sgemm_nt<<<gg, 256>>>(x,   Wq, pQ,  MM, EE, EE);
    sgemm_nt<<<gg, 256>>>(x,   Wk, pK,  MM, EE, EE);
    sgemm_nt<<<gg, 256>>>(x,   Wv, pV,  MM, EE, EE);
    attn_kernel<<<dim3(SS / 64, BB * HH), 256, ATTN_SMEM>>>(pQ, pK, pV, pAO);
    sgemm_nt<<<gg, 256>>>(pAO, Wo, pPO, MM, EE, EE);
    mod_kernel<<<dim3(2 * EE / 256, BB), 256>>>(cond, Wc, bc, pmod);
    rmsfilm_kernel<<<MM, 256>>>(pPO, pmod, rs, out);
}

// round 3
// speedup vs baseline: 1.2934x; 1.2934x over previous
#include <cuda_runtime.h>
#include <cuda_bf16.h>
#include <cstdint>

// Problem constants
#define BB   2
#define SS   2048
#define EE   1024
#define HH   16
#define DD   64
#define CC   256
#define MM   (BB * SS)          // 4096 rows
#define GK   (3 * EE)           // 3072 = split-bf16 expanded K

// ---------------------------------------------------------------------------
// Scratch (allocation-free: __device__ globals)
// ---------------------------------------------------------------------------
__device__ float g_Q [MM * EE];
__device__ float g_K [MM * EE];
__device__ float g_V [MM * EE];
__device__ float g_AO[MM * EE];
__device__ float g_PO[MM * EE];
__device__ float g_mod[BB * 2 * EE];
__device__ __nv_bfloat16 g_X3 [MM * GK];     // split activations [hi|lo|hi]
__device__ __nv_bfloat16 g_AO3[MM * GK];
__device__ __nv_bfloat16 g_W3q[EE * GK];     // split weights     [hi|hi|lo]
__device__ __nv_bfloat16 g_W3k[EE * GK];
__device__ __nv_bfloat16 g_W3v[EE * GK];
__device__ __nv_bfloat16 g_W3o[EE * GK];

// ---------------------------------------------------------------------------
// PTX helpers (base ISA only: cp.async + ldmatrix + mma.sync, sm_80+)
// ---------------------------------------------------------------------------
__device__ __forceinline__ uint32_t smem_u32(const void* p) {
    uint32_t a;
    asm("{ .reg .u64 t; cvta.to.shared.u64 t, %1; cvt.u32.u64 %0, t; }"
        : "=r"(a) : "l"(p));
    return a;
}

#define CP_ASYNC16(sa, ga) \
    asm volatile("cp.async.cg.shared.global [%0], [%1], 16;" :: "r"(sa), "l"(ga))
#define CP_COMMIT() asm volatile("cp.async.commit_group;" ::: "memory")
#define CP_WAIT1()  asm volatile("cp.async.wait_group 1;"  ::: "memory")
#define CP_WAIT0()  asm volatile("cp.async.wait_group 0;"  ::: "memory")

#define LDSM4(r0, r1, r2, r3, addr)                                            \
    asm volatile("ldmatrix.sync.aligned.m8n8.x4.shared.b16 {%0,%1,%2,%3}, [%4];" \
        : "=r"(r0), "=r"(r1), "=r"(r2), "=r"(r3) : "r"(addr))

#define MMA16816(d, a, b0v, b1v)                                               \
    asm volatile("mma.sync.aligned.m16n8k16.row.col.f32.bf16.bf16.f32 "        \
        "{%0,%1,%2,%3}, {%4,%5,%6,%7}, {%8,%9}, {%0,%1,%2,%3};"                \
        : "+f"((d)[0]), "+f"((d)[1]), "+f"((d)[2]), "+f"((d)[3])               \
        : "r"((a)[0]), "r"((a)[1]), "r"((a)[2]), "r"((a)[3]),                  \
          "r"(b0v), "r"(b1v))

// ---------------------------------------------------------------------------
// Split-bf16 conversion kernels
// A3 (activations): [hi | lo | hi];  B3 (weights): [hi | hi | lo]
// A3 . B3^T over 3K = ahi.bhi + alo.bhi + ahi.blo  (~fp32 accuracy)
// ---------------------------------------------------------------------------
__global__ __launch_bounds__(256) void conv_act(const float* __restrict__ in,
                                                __nv_bfloat16* __restrict__ out,
                                                int total)
{
    int i = blockIdx.x * 256 + threadIdx.x;
    if (i >= total) return;
    int r = i >> 10, c = i & (EE - 1);
    float a = in[i];
    __nv_bfloat16 hi = __float2bfloat16(a);
    __nv_bfloat16 lo = __float2bfloat16(a - __bfloat162float(hi));
    size_t o = (size_t)r * GK + c;
    out[o] = hi; out[o + EE] = lo; out[o + 2 * EE] = hi;
}

__global__ __launch_bounds__(256) void conv_w(const float* __restrict__ in,
                                              __nv_bfloat16* __restrict__ out,
                                              int total)
{
    int i = blockIdx.x * 256 + threadIdx.x;
    if (i >= total) return;
    int r = i >> 10, c = i & (EE - 1);
    float a = in[i];
    __nv_bfloat16 hi = __float2bfloat16(a);
    __nv_bfloat16 lo = __float2bfloat16(a - __bfloat162float(hi));
    size_t o = (size_t)r * GK + c;
    out[o] = hi; out[o + EE] = hi; out[o + 2 * EE] = lo;
}

// ---------------------------------------------------------------------------
// bf16 mma.sync GEMM: C[M,N] = A3[M,GK] . B3[N,GK]^T, fp32 out.
// 128x128 CTA tile, BK=32, 256 threads (8 warps, 2x4 grid -> 64x32 per warp).
// Double-buffered cp.async; ldmatrix row stride 40 elems (80B = 5x16B, odd ->
// conflict-free ldmatrix phases).
// ---------------------------------------------------------------------------
#define BKC 32
#define ASTR 40                        // bf16 elems per smem row (32 + 8 pad)
#define NCHUNK (GK / BKC)              // 96

__global__ __launch_bounds__(256) void mma_gemm(const __nv_bfloat16* __restrict__ A3,
                                                const __nv_bfloat16* __restrict__ B3,
                                                float* __restrict__ C, int N)
{
    __shared__ __nv_bfloat16 As[2][128 * ASTR];
    __shared__ __nv_bfloat16 Bs[2][128 * ASTR];

    const int tid  = threadIdx.x;
    const int lane = tid & 31;
    const int wid  = tid >> 5;
    const int wm   = wid >> 2;          // 0..1
    const int wn   = wid & 3;           // 0..3
    const int n0   = blockIdx.x * 128;
    const int m0   = blockIdx.y * 128;

    const uint32_t sA[2] = { smem_u32(As[0]), smem_u32(As[1]) };
    const uint32_t sB[2] = { smem_u32(Bs[0]), smem_u32(Bs[1]) };

    // load granules: 512 16B-granules per tile, 2 per thread per operand
    const int g0r = (tid * 2)     >> 2, g0q = (tid * 2)     & 3;
    const int g1r = (tid * 2 + 1) >> 2, g1q = (tid * 2 + 1) & 3;

    auto load_chunk = [&](int c, int b) {
        const int k0 = c * BKC;
        CP_ASYNC16(sA[b] + (g0r * ASTR + g0q * 8) * 2,
                   A3 + (size_t)(m0 + g0r) * GK + k0 + g0q * 8);
        CP_ASYNC16(sA[b] + (g1r * ASTR + g1q * 8) * 2,
                   A3 + (size_t)(m0 + g1r) * GK + k0 + g1q * 8);
        CP_ASYNC16(sB[b] + (g0r * ASTR + g0q * 8) * 2,
                   B3 + (size_t)(n0 + g0r) * GK + k0 + g0q * 8);
        CP_ASYNC16(sB[b] + (g1r * ASTR + g1q * 8) * 2,
                   B3 + (size_t)(n0 + g1r) * GK + k0 + g1q * 8);
        CP_COMMIT();
    };

    float acc[4][4][4];
#pragma unroll
    for (int i = 0; i < 4; i++)
#pragma unroll
        for (int j = 0; j < 4; j++)
#pragma unroll
            for (int r = 0; r < 4; r++) acc[i][j][r] = 0.f;

    // ldmatrix base offsets (bytes), per-thread
    const uint32_t aRow = (uint32_t)(wm * 64 + (lane & 15));
    const uint32_t aKof = (uint32_t)((lane >> 4) * 8);
    const uint32_t bRow = (uint32_t)(wn * 32 + (lane & 7) + ((lane >> 4) & 1) * 8);
    const uint32_t bKof = (uint32_t)(((lane >> 3) & 1) * 8);

    load_chunk(0, 0);

    for (int c = 0; c < NCHUNK; c++) {
        const int b = c & 1;
        if (c + 1 < NCHUNK) { load_chunk(c + 1, b ^ 1); CP_WAIT1(); }
        else                { CP_WAIT0(); }
        __syncthreads();

#pragma unroll
        for (int ks = 0; ks < 2; ks++) {
            uint32_t a[4][4];
#pragma unroll
            for (int mf = 0; mf < 4; mf++) {
                uint32_t addr = sA[b] +
                    ((aRow + mf * 16) * ASTR + ks * 16 + aKof) * 2;
                LDSM4(a[mf][0], a[mf][1], a[mf][2], a[mf][3], addr);
            }
            uint32_t bf[2][4];
#pragma unroll
            for (int nh = 0; nh < 2; nh++) {
                uint32_t addr = sB[b] +
                    ((bRow + nh * 16) * ASTR + ks * 16 + bKof) * 2;
                LDSM4(bf[nh][0], bf[nh][1], bf[nh][2], bf[nh][3], addr);
            }
#pragma unroll
            for (int mf = 0; mf < 4; mf++)
#pragma unroll
                for (int nf = 0; nf < 4; nf++)
                    MMA16816(acc[mf][nf], a[mf],
                             bf[nf >> 1][(nf & 1) * 2],
                             bf[nf >> 1][(nf & 1) * 2 + 1]);
        }
        __syncthreads();
    }

    // epilogue: c0,c1 at (row, col), c2,c3 at (row+8, col); col 2-aligned
    const int erow = m0 + wm * 64 + (lane >> 2);
    const int ecol = n0 + wn * 32 + (lane & 3) * 2;
#pragma unroll
    for (int mf = 0; mf < 4; mf++) {
#pragma unroll
        for (int nf = 0; nf < 4; nf++) {
            float* p0 = C + (size_t)(erow + mf * 16)     * N + ecol + nf * 8;
            float* p1 = C + (size_t)(erow + mf * 16 + 8) * N + ecol + nf * 8;
            *(float2*)p0 = make_float2(acc[mf][nf][0], acc[mf][nf][1]);
            *(float2*)p1 = make_float2(acc[mf][nf][2], acc[mf][nf][3]);
        }
    }
}

// ---------------------------------------------------------------------------
// Flash attention, fp32, causal (unchanged).
// ---------------------------------------------------------------------------
#define PADR 68
#define ATTN_SMEM (4 * 64 * PADR * 4)

__global__ __launch_bounds__(256) void attn_kernel(const float* __restrict__ Q,
                                                   const float* __restrict__ Kg,
                                                   const float* __restrict__ Vg,
                                                   float* __restrict__ Og)
{
    extern __shared__ float smf[];
    float* Qk  = smf;
    float* Kts = smf + 64 * PADR;
    float* Vs  = smf + 2 * 64 * PADR;
    float* Pt  = smf + 3 * 64 * PADR;

    const int tid = threadIdx.x;
    const int tc  = tid & 15;
    const int tr  = tid >> 4;
    const int qt  = blockIdx.x;
    const int bh  = blockIdx.y;
    const int b   = bh >> 4;
    const int h   = bh & 15;
    const int q0  = qt * 64;
    const size_t base = ((size_t)b * SS) * EE + (size_t)h * DD;

#pragma unroll
    for (int i = 0; i < 4; i++) {
        int idx = tid + i * 256;
        int r   = idx >> 4;
        int kq  = (idx & 15) * 4;
        float4 v = *(const float4*)(Q + base + (size_t)(q0 + r) * EE + kq);
        Qk[(kq + 0) * PADR + r] = v.x;
        Qk[(kq + 1) * PADR + r] = v.y;
        Qk[(kq + 2) * PADR + r] = v.z;
        Qk[(kq + 3) * PADR + r] = v.w;
    }

    float m_i[4], l_i[4], o[4][4];
#pragma unroll
    for (int i = 0; i < 4; i++) {
        m_i[i] = -1e30f; l_i[i] = 0.f;
#pragma unroll
        for (int j = 0; j < 4; j++) o[i][j] = 0.f;
    }

    for (int kt = 0; kt <= qt; kt++) {
        const int k0 = kt * 64;
        __syncthreads();
#pragma unroll
        for (int i = 0; i < 4; i++) {
            int idx = tid + i * 256;
            int r   = idx >> 4;
            int kq  = (idx & 15) * 4;
            float4 vk = *(const float4*)(Kg + base + (size_t)(k0 + r) * EE + kq);
            Kts[(kq + 0) * PADR + r] = vk.x;
            Kts[(kq + 1) * PADR + r] = vk.y;
            Kts[(kq + 2) * PADR + r] = vk.z;
            Kts[(kq + 3) * PADR + r] = vk.w;
            float4 vv = *(const float4*)(Vg + base + (size_t)(k0 + r) * EE + kq);
            *(float4*)(Vs + r * PADR + kq) = vv;
        }
        __syncthreads();

        float s[4][4];
#pragma unroll
        for (int i = 0; i < 4; i++)
#pragma unroll
            for (int j = 0; j < 4; j++) s[i][j] = 0.f;

#pragma unroll 16
        for (int k = 0; k < 64; k++) {
            float4 af = *(const float4*)(Qk  + k * PADR + tr * 4);
            float4 bfv = *(const float4*)(Kts + k * PADR + tc * 4);
            float av[4] = {af.x, af.y, af.z, af.w};
            float bv[4] = {bfv.x, bfv.y, bfv.z, bfv.w};
#pragma unroll
            for (int i = 0; i < 4; i++)
#pragma unroll
                for (int j = 0; j < 4; j++)
                    s[i][j] += av[i] * bv[j];
        }

        const bool diag = (kt == qt);
#pragma unroll
        for (int i = 0; i < 4; i++) {
            int row = tr * 4 + i;
#pragma unroll
            for (int j = 0; j < 4; j++) {
                float v = s[i][j] * 0.125f;
                if (diag && (tc * 4 + j > row)) v = -1e30f;
                s[i][j] = v;
            }
        }

#pragma unroll
        for (int i = 0; i < 4; i++) {
            float mx = fmaxf(fmaxf(s[i][0], s[i][1]), fmaxf(s[i][2], s[i][3]));
#pragma unroll
            for (int off = 8; off >= 1; off >>= 1)
                mx = fmaxf(mx, __shfl_xor_sync(0xffffffffu, mx, off));
            float m_new = fmaxf(m_i[i], mx);
            float corr  = __expf(m_i[i] - m_new);
            float p0 = __expf(s[i][0] - m_new);
            float p1 = __expf(s[i][1] - m_new);
            float p2 = __expf(s[i][2] - m_new);
            float p3 = __expf(s[i][3] - m_new);
            float psum = (p0 + p1) + (p2 + p3);
#pragma unroll
            for (int off = 8; off >= 1; off >>= 1)
                psum += __shfl_xor_sync(0xffffffffu, psum, off);
            l_i[i] = l_i[i] * corr + psum;
            m_i[i] = m_new;
            o[i][0] *= corr; o[i][1] *= corr; o[i][2] *= corr; o[i][3] *= corr;
            Pt[(tc * 4 + 0) * PADR + tr * 4 + i] = p0;
            Pt[(tc * 4 + 1) * PADR + tr * 4 + i] = p1;
            Pt[(tc * 4 + 2) * PADR + tr * 4 + i] = p2;
            Pt[(tc * 4 + 3) * PADR + tr * 4 + i] = p3;
        }
        __syncthreads();

#pragma unroll 16
        for (int col = 0; col < 64; col++) {
            float4 pf = *(const float4*)(Pt + col * PADR + tr * 4);
            float4 vf = *(const float4*)(Vs + col * PADR + tc * 4);
            float pv[4] = {pf.x, pf.y, pf.z, pf.w};
            float vv[4] = {vf.x, vf.y, vf.z, vf.w};
#pragma unroll
            for (int i = 0; i < 4; i++)
#pragma unroll
                for (int j = 0; j < 4; j++)
                    o[i][j] += pv[i] * vv[j];
        }
    }

#pragma unroll
    for (int i = 0; i < 4; i++) {
        float inv = 1.0f / l_i[i];
        float4 r4 = make_float4(o[i][0] * inv, o[i][1] * inv,
                                o[i][2] * inv, o[i][3] * inv);
        *(float4*)(Og + base + (size_t)(q0 + tr * 4 + i) * EE + tc * 4) = r4;
    }
}

// ---------------------------------------------------------------------------
// mod = silu(conditioning) @ Wc.T + bc      (B, 2E)
// ---------------------------------------------------------------------------
__global__ __launch_bounds__(256) void mod_kernel(const float* __restrict__ cond,
                                                  const float* __restrict__ Wc,
                                                  const float* __restrict__ bc,
                                                  float* __restrict__ mod)
{
    __shared__ float scd[CC];
    const int b = blockIdx.y;
    const int t = threadIdx.x;
    float cv = cond[b * CC + t];
    scd[t] = cv / (1.f + __expf(-cv));
    __syncthreads();
    const int j = blockIdx.x * 256 + t;
    const float* w = Wc + (size_t)j * CC;
    float sum = bc[j];
#pragma unroll 8
    for (int c = 0; c < CC; c++) sum += scd[c] * w[c];
    mod[b * 2 * EE + j] = sum;
}

// ---------------------------------------------------------------------------
// AdaptiveRMSNorm + FiLM
// ---------------------------------------------------------------------------
__global__ __launch_bounds__(256) void rmsfilm_kernel(const float* __restrict__ P,
                                                      const float* __restrict__ mod,
                                                      const float* __restrict__ gscale,
                                                      float* __restrict__ out)
{
    const int m = blockIdx.x;
    const int b = m >> 11;
    const int t = threadIdx.x;
    const float* row = P + (size_t)m * EE;
    float4 v = *(const float4*)(row + t * 4);
    float ss = v.x * v.x + v.y * v.y + v.z * v.z + v.w * v.w;
#pragma unroll
    for (int off = 16; off >= 1; off >>= 1)
        ss += __shfl_xor_sync(0xffffffffu, ss, off);
    __shared__ float red[8];
    if ((t & 31) == 0) red[t >> 5] = ss;
    __syncthreads();
    float total = 0.f;
#pragma unroll
    for (int w = 0; w < 8; w++) total += red[w];
    float inv = rsqrtf(total * (1.0f / (float)EE) + 1e-6f);

    const int j = t * 4;
    float4 g  = *(const float4*)(gscale + j);
    float4 sh = *(const float4*)(mod + b * 2 * EE + j);
    float4 sc = *(const float4*)(mod + b * 2 * EE + EE + j);
    float4 r;
    r.x = v.x * inv * g.x * (1.f + sc.x) + sh.x;
    r.y = v.y * inv * g.y * (1.f + sc.y) + sh.y;
    r.z = v.z * inv * g.z * (1.f + sc.z) + sh.z;
    r.w = v.w * inv * g.w * (1.f + sc.w) + sh.w;
    *(float4*)(out + (size_t)m * EE + j) = r;
}

// ---------------------------------------------------------------------------
// launch
// ---------------------------------------------------------------------------
extern "C" void kernel_launch(void* const* d_in, const int* in_sizes, int n_in,
                              void* d_out, int out_size)
{
    const float* x    = (const float*)d_in[0];
    const float* cond = (const float*)d_in[2];
    const float* Wq   = (const float*)d_in[3];
    const float* Wk   = (const float*)d_in[4];
    const float* Wv   = (const float*)d_in[5];
    const float* Wo   = (const float*)d_in[6];
    const float* rs   = (const float*)d_in[7];
    const float* Wc   = (const float*)d_in[8];
    const float* bc   = (const float*)d_in[9];
    float* out = (float*)d_out;

    float *pQ, *pK, *pV, *pAO, *pPO, *pmod;
    __nv_bfloat16 *pX3, *pAO3, *pW3q, *pW3k, *pW3v, *pW3o;
    cudaGetSymbolAddress((void**)&pQ,   g_Q);
    cudaGetSymbolAddress((void**)&pK,   g_K);
    cudaGetSymbolAddress((void**)&pV,   g_V);
    cudaGetSymbolAddress((void**)&pAO,  g_AO);
    cudaGetSymbolAddress((void**)&pPO,  g_PO);
    cudaGetSymbolAddress((void**)&pmod, g_mod);
    cudaGetSymbolAddress((void**)&pX3,  g_X3);
    cudaGetSymbolAddress((void**)&pAO3, g_AO3);
    cudaGetSymbolAddress((void**)&pW3q, g_W3q);
    cudaGetSymbolAddress((void**)&pW3k, g_W3k);
    cudaGetSymbolAddress((void**)&pW3v, g_W3v);
    cudaGetSymbolAddress((void**)&pW3o, g_W3o);

    cudaFuncSetAttribute(attn_kernel,
                         cudaFuncAttributeMaxDynamicSharedMemorySize, ATTN_SMEM);

    const int actN = MM * EE;
    const int wN   = EE * EE;

    conv_act<<<(actN + 255) / 256, 256>>>(x, pX3, actN);
    conv_w  <<<(wN + 255) / 256, 256>>>(Wq, pW3q, wN);
    conv_w  <<<(wN + 255) / 256, 256>>>(Wk, pW3k, wN);
    conv_w  <<<(wN + 255) / 256, 256>>>(Wv, pW3v, wN);
    conv_w  <<<(wN + 255) / 256, 256>>>(Wo, pW3o, wN);

    dim3 gg(EE / 128, MM / 128);   // (8, 32)
    mma_gemm<<<gg, 256>>>(pX3, pW3q, pQ, EE);
    mma_gemm<<<gg, 256>>>(pX3, pW3k, pK, EE);
    mma_gemm<<<gg, 256>>>(pX3, pW3v, pV, EE);

    attn_kernel<<<dim3(SS / 64, BB * HH), 256, ATTN_SMEM>>>(pQ, pK, pV, pAO);

    conv_act<<<(actN + 255) / 256, 256>>>(pAO, pAO3, actN);
    mma_gemm<<<gg, 256>>>(pAO3, pW3o, pPO, EE);

    mod_kernel<<<dim3(2 * EE / 256, BB), 256>>>(cond, Wc, bc, pmod);
    rmsfilm_kernel<<<MM, 256>>>(pPO, pmod, rs, out);
}

// round 4
// speedup vs baseline: 1.6116x; 1.2460x over previous
#include <cuda_runtime.h>
#include <cuda_bf16.h>
#include <cstdint>

// Problem constants
#define BB   2
#define SS   2048
#define EE   1024
#define HH   16
#define DD   64
#define CC   256
#define MM   (BB * SS)          // 4096 rows
#define GK   (3 * EE)           // 3072 = split-bf16 expanded K

// ---------------------------------------------------------------------------
// Scratch (allocation-free: __device__ globals)
// ---------------------------------------------------------------------------
__device__ float g_Q [MM * EE];
__device__ float g_K [MM * EE];
__device__ float g_V [MM * EE];
__device__ float g_PO[MM * EE];
__device__ float g_mod[BB * 2 * EE];
__device__ __nv_bfloat16 g_X3 [MM * GK];     // split activations [hi|lo|hi]
__device__ __nv_bfloat16 g_AO3[MM * GK];     // attn out, split (written by attn)
__device__ __nv_bfloat16 g_W3q[EE * GK];     // split weights     [hi|hi|lo]
__device__ __nv_bfloat16 g_W3k[EE * GK];
__device__ __nv_bfloat16 g_W3v[EE * GK];
__device__ __nv_bfloat16 g_W3o[EE * GK];

// ---------------------------------------------------------------------------
// PTX helpers (base ISA only: cp.async + ldmatrix + mma.sync)
// ---------------------------------------------------------------------------
__device__ __forceinline__ uint32_t smem_u32(const void* p) {
    uint32_t a;
    asm("{ .reg .u64 t; cvta.to.shared.u64 t, %1; cvt.u32.u64 %0, t; }"
        : "=r"(a) : "l"(p));
    return a;
}

#define CP_ASYNC16(sa, ga) \
    asm volatile("cp.async.cg.shared.global [%0], [%1], 16;" :: "r"(sa), "l"(ga))
#define CP_COMMIT() asm volatile("cp.async.commit_group;" ::: "memory")
#define CP_WAIT1()  asm volatile("cp.async.wait_group 1;"  ::: "memory")
#define CP_WAIT0()  asm volatile("cp.async.wait_group 0;"  ::: "memory")

#define LDSM4(r0, r1, r2, r3, addr)                                            \
    asm volatile("ldmatrix.sync.aligned.m8n8.x4.shared.b16 {%0,%1,%2,%3}, [%4];" \
        : "=r"(r0), "=r"(r1), "=r"(r2), "=r"(r3) : "r"(addr))

#define MMA16816(d, a, b0v, b1v)                                               \
    asm volatile("mma.sync.aligned.m16n8k16.row.col.f32.bf16.bf16.f32 "        \
        "{%0,%1,%2,%3}, {%4,%5,%6,%7}, {%8,%9}, {%0,%1,%2,%3};"                \
        : "+f"((d)[0]), "+f"((d)[1]), "+f"((d)[2]), "+f"((d)[3])               \
        : "r"((a)[0]), "r"((a)[1]), "r"((a)[2]), "r"((a)[3]),                  \
          "r"(b0v), "r"(b1v))

__device__ __forceinline__ __nv_bfloat162 split_hi2(float a, float b,
                                                    __nv_bfloat162& lo2) {
    __nv_bfloat16 ha = __float2bfloat16(a);
    __nv_bfloat16 hb = __float2bfloat16(b);
    lo2 = __nv_bfloat162(__float2bfloat16(a - __bfloat162float(ha)),
                         __float2bfloat16(b - __bfloat162float(hb)));
    return __nv_bfloat162(ha, hb);
}

// ---------------------------------------------------------------------------
// Split-bf16 conversion kernels (input-side)
// ---------------------------------------------------------------------------
__global__ __launch_bounds__(256) void conv_act(const float* __restrict__ in,
                                                __nv_bfloat16* __restrict__ out,
                                                int total)
{
    int i = blockIdx.x * 256 + threadIdx.x;
    if (i >= total) return;
    int r = i >> 10, c = i & (EE - 1);
    float a = in[i];
    __nv_bfloat16 hi = __float2bfloat16(a);
    __nv_bfloat16 lo = __float2bfloat16(a - __bfloat162float(hi));
    size_t o = (size_t)r * GK + c;
    out[o] = hi; out[o + EE] = lo; out[o + 2 * EE] = hi;
}

__global__ __launch_bounds__(256) void conv_w(const float* __restrict__ in,
                                              __nv_bfloat16* __restrict__ out,
                                              int total)
{
    int i = blockIdx.x * 256 + threadIdx.x;
    if (i >= total) return;
    int r = i >> 10, c = i & (EE - 1);
    float a = in[i];
    __nv_bfloat16 hi = __float2bfloat16(a);
    __nv_bfloat16 lo = __float2bfloat16(a - __bfloat162float(hi));
    size_t o = (size_t)r * GK + c;
    out[o] = hi; out[o + EE] = hi; out[o + 2 * EE] = lo;
}

// ---------------------------------------------------------------------------
// bf16 mma.sync GEMM (validated round 3)
// ---------------------------------------------------------------------------
#define BKC 32
#define ASTR 40
#define NCHUNK (GK / BKC)

__global__ __launch_bounds__(256) void mma_gemm(const __nv_bfloat16* __restrict__ A3,
                                                const __nv_bfloat16* __restrict__ B3,
                                                float* __restrict__ C, int N)
{
    __shared__ __nv_bfloat16 As[2][128 * ASTR];
    __shared__ __nv_bfloat16 Bs[2][128 * ASTR];

    const int tid  = threadIdx.x;
    const int lane = tid & 31;
    const int wid  = tid >> 5;
    const int wm   = wid >> 2;
    const int wn   = wid & 3;
    const int n0   = blockIdx.x * 128;
    const int m0   = blockIdx.y * 128;

    const uint32_t sA[2] = { smem_u32(As[0]), smem_u32(As[1]) };
    const uint32_t sB[2] = { smem_u32(Bs[0]), smem_u32(Bs[1]) };

    const int g0r = (tid * 2)     >> 2, g0q = (tid * 2)     & 3;
    const int g1r = (tid * 2 + 1) >> 2, g1q = (tid * 2 + 1) & 3;

    auto load_chunk = [&](int c, int b) {
        const int k0 = c * BKC;
        CP_ASYNC16(sA[b] + (g0r * ASTR + g0q * 8) * 2,
                   A3 + (size_t)(m0 + g0r) * GK + k0 + g0q * 8);
        CP_ASYNC16(sA[b] + (g1r * ASTR + g1q * 8) * 2,
                   A3 + (size_t)(m0 + g1r) * GK + k0 + g1q * 8);
        CP_ASYNC16(sB[b] + (g0r * ASTR + g0q * 8) * 2,
                   B3 + (size_t)(n0 + g0r) * GK + k0 + g0q * 8);
        CP_ASYNC16(sB[b] + (g1r * ASTR + g1q * 8) * 2,
                   B3 + (size_t)(n0 + g1r) * GK + k0 + g1q * 8);
        CP_COMMIT();
    };

    float acc[4][4][4];
#pragma unroll
    for (int i = 0; i < 4; i++)
#pragma unroll
        for (int j = 0; j < 4; j++)
#pragma unroll
            for (int r = 0; r < 4; r++) acc[i][j][r] = 0.f;

    const uint32_t aRow = (uint32_t)(wm * 64 + (lane & 15));
    const uint32_t aKof = (uint32_t)((lane >> 4) * 8);
    const uint32_t bRow = (uint32_t)(wn * 32 + (lane & 7) + ((lane >> 4) & 1) * 8);
    const uint32_t bKof = (uint32_t)(((lane >> 3) & 1) * 8);

    load_chunk(0, 0);

    for (int c = 0; c < NCHUNK; c++) {
        const int b = c & 1;
        if (c + 1 < NCHUNK) { load_chunk(c + 1, b ^ 1); CP_WAIT1(); }
        else                { CP_WAIT0(); }
        __syncthreads();

#pragma unroll
        for (int ks = 0; ks < 2; ks++) {
            uint32_t a[4][4];
#pragma unroll
            for (int mf = 0; mf < 4; mf++) {
                uint32_t addr = sA[b] +
                    ((aRow + mf * 16) * ASTR + ks * 16 + aKof) * 2;
                LDSM4(a[mf][0], a[mf][1], a[mf][2], a[mf][3], addr);
            }
            uint32_t bf[2][4];
#pragma unroll
            for (int nh = 0; nh < 2; nh++) {
                uint32_t addr = sB[b] +
                    ((bRow + nh * 16) * ASTR + ks * 16 + bKof) * 2;
                LDSM4(bf[nh][0], bf[nh][1], bf[nh][2], bf[nh][3], addr);
            }
#pragma unroll
            for (int mf = 0; mf < 4; mf++)
#pragma unroll
                for (int nf = 0; nf < 4; nf++)
                    MMA16816(acc[mf][nf], a[mf],
                             bf[nf >> 1][(nf & 1) * 2],
                             bf[nf >> 1][(nf & 1) * 2 + 1]);
        }
        __syncthreads();
    }

    const int erow = m0 + wm * 64 + (lane >> 2);
    const int ecol = n0 + wn * 32 + (lane & 3) * 2;
#pragma unroll
    for (int mf = 0; mf < 4; mf++) {
#pragma unroll
        for (int nf = 0; nf < 4; nf++) {
            float* p0 = C + (size_t)(erow + mf * 16)     * N + ecol + nf * 8;
            float* p1 = C + (size_t)(erow + mf * 16 + 8) * N + ecol + nf * 8;
            *(float2*)p0 = make_float2(acc[mf][nf][0], acc[mf][nf][1]);
            *(float2*)p1 = make_float2(acc[mf][nf][2], acc[mf][nf][3]);
        }
    }
}

// ---------------------------------------------------------------------------
// Tensor-core flash attention, split-bf16, causal.
// CTA = 64 q-rows of one (b,h), 128 threads (4 warps, each m16 slice).
// QK^T over D3=192 (split), softmax fp32 in fragments, PV over t'=192 (split P,
// V transposed in smem so B operand uses the validated non-trans ldmatrix).
// Output: split-bf16 AO3 directly.
// ---------------------------------------------------------------------------
#define D3   192
#define AS3  200     // bf16 row stride (odd multiple of 8 -> ldsm conflict-free)
#define ATTN_SMEM (4 * 64 * AS3 * 2)   // Q3, K3, Vt3, P3 = 102400 bytes

__global__ __launch_bounds__(128) void attn_mma(const float* __restrict__ Qg,
                                                const float* __restrict__ Kg,
                                                const float* __restrict__ Vg,
                                                __nv_bfloat16* __restrict__ AO3)
{
    extern __shared__ __align__(16) char smc[];
    __nv_bfloat16* Q3  = (__nv_bfloat16*)smc;
    __nv_bfloat16* K3  = Q3  + 64 * AS3;
    __nv_bfloat16* Vt3 = K3  + 64 * AS3;
    __nv_bfloat16* P3  = Vt3 + 64 * AS3;
    const uint32_t uQ3 = smem_u32(Q3), uK3 = smem_u32(K3);
    const uint32_t uV3 = smem_u32(Vt3), uP3 = smem_u32(P3);

    const int tid  = threadIdx.x;
    const int lane = tid & 31;
    const int w    = tid >> 5;
    const int qt   = blockIdx.x;
    const int bh   = blockIdx.y;
    const int b    = bh >> 4;
    const int h    = bh & 15;
    const int q0   = qt * 64;
    const size_t base = ((size_t)b * SS) * EE + (size_t)h * DD;

    // ---- load + split Q tile (64 x 64 fp32 -> 64 x 192 bf16 [hi|lo|hi]) ----
#pragma unroll
    for (int i = 0; i < 8; i++) {
        int idx = tid + i * 128;       // 0..1023
        int r   = idx >> 4;
        int c   = (idx & 15) * 4;
        float4 v = *(const float4*)(Qg + base + (size_t)(q0 + r) * EE + c);
        __nv_bfloat162 lo0, lo1;
        __nv_bfloat162 hi0 = split_hi2(v.x, v.y, lo0);
        __nv_bfloat162 hi1 = split_hi2(v.z, v.w, lo1);
        __nv_bfloat16* row = Q3 + r * AS3;
        *(__nv_bfloat162*)(row + c)           = hi0;
        *(__nv_bfloat162*)(row + c + 2)       = hi1;
        *(__nv_bfloat162*)(row + 64 + c)      = lo0;
        *(__nv_bfloat162*)(row + 64 + c + 2)  = lo1;
        *(__nv_bfloat162*)(row + 128 + c)     = hi0;
        *(__nv_bfloat162*)(row + 128 + c + 2) = hi1;
    }

    // fragment-constant addressing (validated in mma_gemm)
    const uint32_t aRow = (uint32_t)(w * 16 + (lane & 15));
    const uint32_t aKof = (uint32_t)((lane >> 4) * 8);
    const uint32_t bRow = (uint32_t)((lane & 7) + ((lane >> 4) & 1) * 8);
    const uint32_t bKof = (uint32_t)(((lane >> 3) & 1) * 8);

    const int rloc0 = w * 16 + (lane >> 2);     // local q row (first)
    const int cbase = (lane & 3) * 2;

    float m_i[2] = {-1e30f, -1e30f};
    float l_i[2] = {0.f, 0.f};
    float o[8][4];
#pragma unroll
    for (int nf = 0; nf < 8; nf++)
#pragma unroll
        for (int r = 0; r < 4; r++) o[nf][r] = 0.f;

    for (int kt = 0; kt <= qt; kt++) {
        const int k0 = kt * 64;
        __syncthreads();   // previous K3/Vt3 consumed; also covers Q3 on kt=0
        // ---- load + split K tile [hi|hi|lo], V tile transposed ----
#pragma unroll
        for (int i = 0; i < 8; i++) {
            int idx = tid + i * 128;
            int r   = idx >> 4;
            int c   = (idx & 15) * 4;
            float4 vk = *(const float4*)(Kg + base + (size_t)(k0 + r) * EE + c);
            __nv_bfloat162 lo0, lo1;
            __nv_bfloat162 hi0 = split_hi2(vk.x, vk.y, lo0);
            __nv_bfloat162 hi1 = split_hi2(vk.z, vk.w, lo1);
            __nv_bfloat16* row = K3 + r * AS3;
            *(__nv_bfloat162*)(row + c)           = hi0;
            *(__nv_bfloat162*)(row + c + 2)       = hi1;
            *(__nv_bfloat162*)(row + 64 + c)      = hi0;
            *(__nv_bfloat162*)(row + 64 + c + 2)  = hi1;
            *(__nv_bfloat162*)(row + 128 + c)     = lo0;
            *(__nv_bfloat162*)(row + 128 + c + 2) = lo1;

            float4 vv = *(const float4*)(Vg + base + (size_t)(k0 + r) * EE + c);
            float vf[4] = {vv.x, vv.y, vv.z, vv.w};
#pragma unroll
            for (int j = 0; j < 4; j++) {
                __nv_bfloat16 hi = __float2bfloat16(vf[j]);
                __nv_bfloat16 lo = __float2bfloat16(vf[j] - __bfloat162float(hi));
                __nv_bfloat16* vrow = Vt3 + (c + j) * AS3;
                vrow[r]       = hi;     // t' = r
                vrow[64 + r]  = hi;     // t' = 64 + r
                vrow[128 + r] = lo;     // t' = 128 + r
            }
        }
        __syncthreads();

        // ---- S = Q3 . K3^T (m16 x n64, k 192) ----
        float s[8][4];
#pragma unroll
        for (int nf = 0; nf < 8; nf++)
#pragma unroll
            for (int r = 0; r < 4; r++) s[nf][r] = 0.f;

#pragma unroll
        for (int ks = 0; ks < 12; ks++) {
            uint32_t a[4];
            LDSM4(a[0], a[1], a[2], a[3],
                  uQ3 + (aRow * AS3 + ks * 16 + aKof) * 2);
            uint32_t bq[4][4];
#pragma unroll
            for (int nb = 0; nb < 4; nb++)
                LDSM4(bq[nb][0], bq[nb][1], bq[nb][2], bq[nb][3],
                      uK3 + ((nb * 16 + bRow) * AS3 + ks * 16 + bKof) * 2);
#pragma unroll
            for (int nf = 0; nf < 8; nf++)
                MMA16816(s[nf], a, bq[nf >> 1][(nf & 1) * 2],
                                   bq[nf >> 1][(nf & 1) * 2 + 1]);
        }

        // ---- scale + causal mask ----
        const bool diag = (kt == qt);
        const int grow0 = q0 + rloc0;
#pragma unroll
        for (int nf = 0; nf < 8; nf++) {
            int gc = k0 + nf * 8 + cbase;
#pragma unroll
            for (int r = 0; r < 4; r++) {
                float v = s[nf][r] * 0.125f;
                if (diag) {
                    int row = grow0 + (r >> 1) * 8;
                    int col = gc + (r & 1);
                    if (col > row) v = -1e30f;
                }
                s[nf][r] = v;
            }
        }

        // ---- online softmax (rows rloc0, rloc0+8) ----
        float mx0 = -1e30f, mx1 = -1e30f;
#pragma unroll
        for (int nf = 0; nf < 8; nf++) {
            mx0 = fmaxf(mx0, fmaxf(s[nf][0], s[nf][1]));
            mx1 = fmaxf(mx1, fmaxf(s[nf][2], s[nf][3]));
        }
#pragma unroll
        for (int off = 2; off >= 1; off >>= 1) {
            mx0 = fmaxf(mx0, __shfl_xor_sync(0xffffffffu, mx0, off));
            mx1 = fmaxf(mx1, __shfl_xor_sync(0xffffffffu, mx1, off));
        }
        float mn0 = fmaxf(m_i[0], mx0), mn1 = fmaxf(m_i[1], mx1);
        float cr0 = __expf(m_i[0] - mn0), cr1 = __expf(m_i[1] - mn1);
        float ps0 = 0.f, ps1 = 0.f;
#pragma unroll
        for (int nf = 0; nf < 8; nf++) {
            s[nf][0] = __expf(s[nf][0] - mn0);
            s[nf][1] = __expf(s[nf][1] - mn0);
            s[nf][2] = __expf(s[nf][2] - mn1);
            s[nf][3] = __expf(s[nf][3] - mn1);
            ps0 += s[nf][0] + s[nf][1];
            ps1 += s[nf][2] + s[nf][3];
            o[nf][0] *= cr0; o[nf][1] *= cr0;
            o[nf][2] *= cr1; o[nf][3] *= cr1;
        }
#pragma unroll
        for (int off = 2; off >= 1; off >>= 1) {
            ps0 += __shfl_xor_sync(0xffffffffu, ps0, off);
            ps1 += __shfl_xor_sync(0xffffffffu, ps1, off);
        }
        l_i[0] = l_i[0] * cr0 + ps0;
        l_i[1] = l_i[1] * cr1 + ps1;
        m_i[0] = mn0; m_i[1] = mn1;

        // ---- write P3 [hi|lo|hi] (own 16-row slice only) ----
#pragma unroll
        for (int nf = 0; nf < 8; nf++) {
            int c = nf * 8 + cbase;
            __nv_bfloat162 lo, hi;
            hi = split_hi2(s[nf][0], s[nf][1], lo);
            __nv_bfloat16* row = P3 + rloc0 * AS3;
            *(__nv_bfloat162*)(row + c)       = hi;
            *(__nv_bfloat162*)(row + 64 + c)  = lo;
            *(__nv_bfloat162*)(row + 128 + c) = hi;
            hi = split_hi2(s[nf][2], s[nf][3], lo);
            row = P3 + (rloc0 + 8) * AS3;
            *(__nv_bfloat162*)(row + c)       = hi;
            *(__nv_bfloat162*)(row + 64 + c)  = lo;
            *(__nv_bfloat162*)(row + 128 + c) = hi;
        }
        __syncwarp();

        // ---- O += P3 . Vt3^T (m16 x n64=d, k' 192) ----
#pragma unroll
        for (int ks = 0; ks < 12; ks++) {
            uint32_t a[4];
            LDSM4(a[0], a[1], a[2], a[3],
                  uP3 + (aRow * AS3 + ks * 16 + aKof) * 2);
            uint32_t bv[4][4];
#pragma unroll
            for (int nb = 0; nb < 4; nb++)
                LDSM4(bv[nb][0], bv[nb][1], bv[nb][2], bv[nb][3],
                      uV3 + ((nb * 16 + bRow) * AS3 + ks * 16 + bKof) * 2);
#pragma unroll
            for (int nf = 0; nf < 8; nf++)
                MMA16816(o[nf], a, bv[nf >> 1][(nf & 1) * 2],
                                   bv[nf >> 1][(nf & 1) * 2 + 1]);
        }
    }

    // ---- epilogue: normalize, split, store to AO3 ----
    const float inv0 = 1.0f / l_i[0];
    const float inv1 = 1.0f / l_i[1];
    const size_t mrow0 = (size_t)(b * SS + q0 + rloc0);
    const size_t mrow1 = mrow0 + 8;
    const int col0 = h * DD + cbase;
#pragma unroll
    for (int nf = 0; nf < 8; nf++) {
        int c = col0 + nf * 8;
        __nv_bfloat162 lo, hi;
        hi = split_hi2(o[nf][0] * inv0, o[nf][1] * inv0, lo);
        __nv_bfloat16* p = AO3 + mrow0 * GK + c;
        *(__nv_bfloat162*)(p)          = hi;
        *(__nv_bfloat162*)(p + EE)     = lo;
        *(__nv_bfloat162*)(p + 2 * EE) = hi;
        hi = split_hi2(o[nf][2] * inv1, o[nf][3] * inv1, lo);
        p = AO3 + mrow1 * GK + c;
        *(__nv_bfloat162*)(p)          = hi;
        *(__nv_bfloat162*)(p + EE)     = lo;
        *(__nv_bfloat162*)(p + 2 * EE) = hi;
    }
}

// ---------------------------------------------------------------------------
// mod = silu(conditioning) @ Wc.T + bc
// ---------------------------------------------------------------------------
__global__ __launch_bounds__(256) void mod_kernel(const float* __restrict__ cond,
                                                  const float* __restrict__ Wc,
                                                  const float* __restrict__ bc,
                                                  float* __restrict__ mod)
{
    __shared__ float scd[CC];
    const int b = blockIdx.y;
    const int t = threadIdx.x;
    float cv = cond[b * CC + t];
    scd[t] = cv / (1.f + __expf(-cv));
    __syncthreads();
    const int j = blockIdx.x * 256 + t;
    const float* w = Wc + (size_t)j * CC;
    float sum = bc[j];
#pragma unroll 8
    for (int c = 0; c < CC; c++) sum += scd[c] * w[c];
    mod[b * 2 * EE + j] = sum;
}

// ---------------------------------------------------------------------------
// AdaptiveRMSNorm + FiLM
// ---------------------------------------------------------------------------
__global__ __launch_bounds__(256) void rmsfilm_kernel(const float* __restrict__ P,
                                                      const float* __restrict__ mod,
                                                      const float* __restrict__ gscale,
                                                      float* __restrict__ out)
{
    const int m = blockIdx.x;
    const int b = m >> 11;
    const int t = threadIdx.x;
    const float* row = P + (size_t)m * EE;
    float4 v = *(const float4*)(row + t * 4);
    float ss = v.x * v.x + v.y * v.y + v.z * v.z + v.w * v.w;
#pragma unroll
    for (int off = 16; off >= 1; off >>= 1)
        ss += __shfl_xor_sync(0xffffffffu, ss, off);
    __shared__ float red[8];
    if ((t & 31) == 0) red[t >> 5] = ss;
    __syncthreads();
    float total = 0.f;
#pragma unroll
    for (int w = 0; w < 8; w++) total += red[w];
    float inv = rsqrtf(total * (1.0f / (float)EE) + 1e-6f);

    const int j = t * 4;
    float4 g  = *(const float4*)(gscale + j);
    float4 sh = *(const float4*)(mod + b * 2 * EE + j);
    float4 sc = *(const float4*)(mod + b * 2 * EE + EE + j);
    float4 r;
    r.x = v.x * inv * g.x * (1.f + sc.x) + sh.x;
    r.y = v.y * inv * g.y * (1.f + sc.y) + sh.y;
    r.z = v.z * inv * g.z * (1.f + sc.z) + sh.z;
    r.w = v.w * inv * g.w * (1.f + sc.w) + sh.w;
    *(float4*)(out + (size_t)m * EE + j) = r;
}

// ---------------------------------------------------------------------------
// launch
// ---------------------------------------------------------------------------
extern "C" void kernel_launch(void* const* d_in, const int* in_sizes, int n_in,
                              void* d_out, int out_size)
{
    const float* x    = (const float*)d_in[0];
    const float* cond = (const float*)d_in[2];
    const float* Wq   = (const float*)d_in[3];
    const float* Wk   = (const float*)d_in[4];
    const float* Wv   = (const float*)d_in[5];
    const float* Wo   = (const float*)d_in[6];
    const float* rs   = (const float*)d_in[7];
    const float* Wc   = (const float*)d_in[8];
    const float* bc   = (const float*)d_in[9];
    float* out = (float*)d_out;

    float *pQ, *pK, *pV, *pPO, *pmod;
    __nv_bfloat16 *pX3, *pAO3, *pW3q, *pW3k, *pW3v, *pW3o;
    cudaGetSymbolAddress((void**)&pQ,   g_Q);
    cudaGetSymbolAddress((void**)&pK,   g_K);
    cudaGetSymbolAddress((void**)&pV,   g_V);
    cudaGetSymbolAddress((void**)&pPO,  g_PO);
    cudaGetSymbolAddress((void**)&pmod, g_mod);
    cudaGetSymbolAddress((void**)&pX3,  g_X3);
    cudaGetSymbolAddress((void**)&pAO3, g_AO3);
    cudaGetSymbolAddress((void**)&pW3q, g_W3q);
    cudaGetSymbolAddress((void**)&pW3k, g_W3k);
    cudaGetSymbolAddress((void**)&pW3v, g_W3v);
    cudaGetSymbolAddress((void**)&pW3o, g_W3o);

    cudaFuncSetAttribute(attn_mma,
                         cudaFuncAttributeMaxDynamicSharedMemorySize, ATTN_SMEM);

    const int actN = MM * EE;
    const int wN   = EE * EE;

    conv_act<<<(actN + 255) / 256, 256>>>(x, pX3, actN);
    conv_w  <<<(wN + 255) / 256, 256>>>(Wq, pW3q, wN);
    conv_w  <<<(wN + 255) / 256, 256>>>(Wk, pW3k, wN);
    conv_w  <<<(wN + 255) / 256, 256>>>(Wv, pW3v, wN);
    conv_w  <<<(wN + 255) / 256, 256>>>(Wo, pW3o, wN);

    dim3 gg(EE / 128, MM / 128);
    mma_gemm<<<gg, 256>>>(pX3, pW3q, pQ, EE);
    mma_gemm<<<gg, 256>>>(pX3, pW3k, pK, EE);
    mma_gemm<<<gg, 256>>>(pX3, pW3v, pV, EE);

    attn_mma<<<dim3(SS / 64, BB * HH), 128, ATTN_SMEM>>>(pQ, pK, pV, pAO3);

    mma_gemm<<<gg, 256>>>(pAO3, pW3o, pPO, EE);

    mod_kernel<<<dim3(2 * EE / 256, BB), 256>>>(cond, Wc, bc, pmod);
    rmsfilm_kernel<<<MM, 256>>>(pPO, pmod, rs, out);
}